// round 1
// baseline (speedup 1.0000x reference)
#include <cuda_runtime.h>
#include <math.h>

// ---------------- problem constants ----------------
#define BQ 4
#define FQ 8
#define HQ 12
#define DQ 768
#define DHQ 64
#define NPQ 196
#define SQ 1569                  // 1 + 8*196
#define TQ (BQ*SQ)               // 6276 tokens
#define HIDQ 3072
#define LQ 12
#define EPSQ 1e-6f
#define SCALEQ 0.125f            // 64^-0.5

// ---------------- scratch (static device globals; no allocations) ----------------
__device__ float g_xt  [(size_t)TQ*DQ];
__device__ float g_ln  [(size_t)TQ*DQ];
__device__ float g_qkv [(size_t)TQ*3*DQ];
__device__ float g_attn[(size_t)TQ*DQ];
__device__ float g_res [(size_t)TQ*DQ];
__device__ float g_hid [(size_t)TQ*HIDQ];   // also reused as im2col buffer

// ---------------- block reduce helper (256-thread blocks) ----------------
__device__ __forceinline__ float block_red(float v, int isMax) {
    __shared__ float red[8];
    int lane = threadIdx.x & 31, w = threadIdx.x >> 5;
    #pragma unroll
    for (int o = 16; o; o >>= 1) {
        float t = __shfl_xor_sync(0xffffffffu, v, o);
        v = isMax ? fmaxf(v, t) : (v + t);
    }
    __syncthreads();                // protect red[] from previous use
    if (lane == 0) red[w] = v;
    __syncthreads();
    float t = red[0];
    #pragma unroll
    for (int i = 1; i < 8; i++) t = isMax ? fmaxf(t, red[i]) : (t + red[i]);
    return t;
}

// ---------------- im2col for patch embedding ----------------
__global__ void im2col_k(const float* __restrict__ x, float* __restrict__ out) {
    int idx = blockIdx.x * 256 + threadIdx.x;
    if (idx >= 6272 * 768) return;
    int r = idx / 768, c = idx % 768;
    int bf = r / 196, p = r % 196;
    int ph = p / 14, pw = p % 14;
    int ch = c >> 8, rem = c & 255;
    int i = rem >> 4, j = rem & 15;
    size_t off = (((size_t)bf * 3 + ch) * 224 + ph * 16 + i) * 224 + pw * 16 + j;
    out[idx] = x[off];
}

// ---------------- assemble tokens: patch embed + cls + pos + temporal ----------------
__global__ void assemble_k(const float* __restrict__ pe,
                           const float* __restrict__ patch_b,
                           const float* __restrict__ cls_tok,
                           const float* __restrict__ pos,
                           const float* __restrict__ temp,
                           float* __restrict__ xt) {
    int idx = blockIdx.x * 256 + threadIdx.x;
    if (idx >= TQ * DQ) return;
    int t = idx / DQ, dd = idx % DQ;
    int b = t / SQ, s = t % SQ;
    float v;
    if (s == 0) {
        v = cls_tok[dd] + pos[dd];
    } else {
        int sp = s - 1, fr = sp / 196, p = sp % 196;
        v = pe[((size_t)(b * 8 + fr) * 196 + p) * 768 + dd] + patch_b[dd]
            + pos[(size_t)(1 + p) * 768 + dd] + temp[(size_t)fr * 768 + dd];
    }
    xt[idx] = v;
}

// ---------------- layernorm (row = 768) ----------------
__global__ void ln_k(const float* __restrict__ x, const float* __restrict__ sc,
                     const float* __restrict__ bi, float* __restrict__ y) {
    int row = blockIdx.x, tid = threadIdx.x;
    const float* xr = x + (size_t)row * DQ;
    float r0 = xr[tid], r1 = xr[tid + 256], r2 = xr[tid + 512];
    float mean = block_red(r0 + r1 + r2, 0) * (1.f / 768.f);
    float d0 = r0 - mean, d1 = r1 - mean, d2 = r2 - mean;
    float var = block_red(d0 * d0 + d1 * d1 + d2 * d2, 0) * (1.f / 768.f);
    float inv = rsqrtf(var + EPSQ);
    float* yr = y + (size_t)row * DQ;
    yr[tid]       = d0 * inv * sc[tid]       + bi[tid];
    yr[tid + 256] = d1 * inv * sc[tid + 256] + bi[tid + 256];
    yr[tid + 512] = d2 * inv * sc[tid + 512] + bi[tid + 512];
}

// final LN on cls rows only -> output (4,768)
__global__ void final_ln_k(const float* __restrict__ xt, const float* __restrict__ sc,
                           const float* __restrict__ bi, float* __restrict__ out) {
    int b = blockIdx.x, tid = threadIdx.x;
    const float* xr = xt + (size_t)(b * SQ) * DQ;
    float r0 = xr[tid], r1 = xr[tid + 256], r2 = xr[tid + 512];
    float mean = block_red(r0 + r1 + r2, 0) * (1.f / 768.f);
    float d0 = r0 - mean, d1 = r1 - mean, d2 = r2 - mean;
    float var = block_red(d0 * d0 + d1 * d1 + d2 * d2, 0) * (1.f / 768.f);
    float inv = rsqrtf(var + EPSQ);
    float* yr = out + (size_t)b * DQ;
    yr[tid]       = d0 * inv * sc[tid]       + bi[tid];
    yr[tid + 256] = d1 * inv * sc[tid + 256] + bi[tid + 256];
    yr[tid + 512] = d2 * inv * sc[tid + 512] + bi[tid + 512];
}

// ---------------- SGEMM: C = A[M,K] @ W[N,K]^T + bias (+res) (+gelu) ----------------
template<int ACT>
__global__ void __launch_bounds__(256, 2) gemm_k(
    const float* __restrict__ A, const float* __restrict__ W,
    const float* __restrict__ bias, const float* __restrict__ res,
    float* __restrict__ C, int M, int N, int K) {
    __shared__ float As[8][128];
    __shared__ float Bs[8][128];
    int tid = threadIdx.x;
    int bm = blockIdx.y * 128;
    int bn = blockIdx.x * 128;
    int tx = tid & 15, ty = tid >> 4;
    int lr = tid >> 1;
    int lc = (tid & 1) * 4;
    bool aValid = (bm + lr) < M;
    const float* Ag = A + (size_t)(bm + lr) * K + lc;
    const float* Wg = W + (size_t)(bn + lr) * K + lc;
    float acc[8][8];
    #pragma unroll
    for (int i = 0; i < 8; i++)
        #pragma unroll
        for (int j = 0; j < 8; j++) acc[i][j] = 0.f;

    for (int k0 = 0; k0 < K; k0 += 8) {
        float4 av = aValid ? *(const float4*)(Ag + k0) : make_float4(0.f, 0.f, 0.f, 0.f);
        float4 wv = *(const float4*)(Wg + k0);
        As[lc + 0][lr] = av.x; As[lc + 1][lr] = av.y;
        As[lc + 2][lr] = av.z; As[lc + 3][lr] = av.w;
        Bs[lc + 0][lr] = wv.x; Bs[lc + 1][lr] = wv.y;
        Bs[lc + 2][lr] = wv.z; Bs[lc + 3][lr] = wv.w;
        __syncthreads();
        #pragma unroll
        for (int kk = 0; kk < 8; kk++) {
            float a[8], b[8];
            *(float4*)(a)     = *(const float4*)(&As[kk][ty * 8]);
            *(float4*)(a + 4) = *(const float4*)(&As[kk][ty * 8 + 4]);
            *(float4*)(b)     = *(const float4*)(&Bs[kk][tx * 8]);
            *(float4*)(b + 4) = *(const float4*)(&Bs[kk][tx * 8 + 4]);
            #pragma unroll
            for (int i = 0; i < 8; i++)
                #pragma unroll
                for (int j = 0; j < 8; j++)
                    acc[i][j] = fmaf(a[i], b[j], acc[i][j]);
        }
        __syncthreads();
    }
    #pragma unroll
    for (int i = 0; i < 8; i++) {
        int m = bm + ty * 8 + i;
        if (m < M) {
            #pragma unroll
            for (int j = 0; j < 8; j++) {
                int n = bn + tx * 8 + j;
                float v = acc[i][j];
                if (bias) v += bias[n];
                if (res)  v += res[(size_t)m * N + n];
                if (ACT == 1) v = 0.5f * v * (1.f + erff(v * 0.70710678118654752f));
                C[(size_t)m * N + n] = v;
            }
        }
    }
}

// ---------------- cls-row attention: 48 blocks (b,h), full 1569-key softmax ----------------
__global__ void cls_attn_k(const float* __restrict__ qkv, float* __restrict__ outp) {
    __shared__ float sc[SQ];
    __shared__ float qv[64];
    __shared__ float op[256];
    int bh = blockIdx.x, b = bh / 12, h = bh % 12;
    int tid = threadIdx.x;
    size_t base = (size_t)(b * SQ) * 2304 + (size_t)h * 64;
    if (tid < 64) qv[tid] = qkv[base + tid] * SCALEQ;
    __syncthreads();
    float lmax = -1e30f;
    for (int s = tid; s < SQ; s += 256) {
        const float* kp = qkv + (size_t)(b * SQ + s) * 2304 + 768 + h * 64;
        float d = 0.f;
        #pragma unroll
        for (int i = 0; i < 64; i++) d += qv[i] * kp[i];
        sc[s] = d; lmax = fmaxf(lmax, d);
    }
    float mx = block_red(lmax, 1);
    float lsum = 0.f;
    for (int s = tid; s < SQ; s += 256) {
        float e = expf(sc[s] - mx);
        sc[s] = e; lsum += e;
    }
    float den = block_red(lsum, 0);
    __syncthreads();
    int part = tid >> 6, d = tid & 63;
    float acc = 0.f;
    for (int s = part; s < SQ; s += 4)
        acc += sc[s] * qkv[(size_t)(b * SQ + s) * 2304 + 1536 + h * 64 + d];
    op[tid] = acc;
    __syncthreads();
    if (tid < 64) {
        float t = op[tid] + op[tid + 64] + op[tid + 128] + op[tid + 192];
        outp[(size_t)(b * SQ) * 768 + h * 64 + tid] = t / den;
    }
}

// ---------------- space attention: 384 blocks (b,h,frame), K/V in smem ----------------
#define SPACE_SMEM ((197*65*2 + 8*197 + 8*64) * 4)
__global__ void space_attn_k(const float* __restrict__ qkv, float* __restrict__ outp) {
    extern __shared__ float sm[];
    float* Ks = sm;                 // [197][65]
    float* Vs = Ks + 197 * 65;      // [197][65]
    float* pb = Vs + 197 * 65;      // [8][197]
    float* qb = pb + 8 * 197;       // [8][64]
    int blk = blockIdx.x;
    int fr = blk % 8, h = (blk / 8) % 12, b = blk / 96;
    int tid = threadIdx.x, lane = tid & 31, w = tid >> 5;
    for (int idx = tid; idx < 197 * 64; idx += 256) {
        int kk = idx >> 6, d = idx & 63;
        int s = kk ? (1 + fr * 196 + kk - 1) : 0;
        size_t o = (size_t)(b * SQ + s) * 2304 + h * 64;
        Ks[kk * 65 + d] = qkv[o + 768 + d];
        Vs[kk * 65 + d] = qkv[o + 1536 + d];
    }
    __syncthreads();
    for (int qi = w; qi < 196; qi += 8) {
        int sq = 1 + fr * 196 + qi;
        size_t oq = (size_t)(b * SQ + sq) * 2304 + h * 64;
        qb[w * 64 + lane]      = qkv[oq + lane] * SCALEQ;
        qb[w * 64 + lane + 32] = qkv[oq + lane + 32] * SCALEQ;
        __syncwarp();
        float ls[7];
        float lmax = -1e30f;
        int cnt = 0;
        for (int kk = lane; kk < 197; kk += 32) {
            float s = 0.f;
            #pragma unroll
            for (int d = 0; d < 64; d++) s += qb[w * 64 + d] * Ks[kk * 65 + d];
            ls[cnt++] = s; lmax = fmaxf(lmax, s);
        }
        #pragma unroll
        for (int o = 16; o; o >>= 1) lmax = fmaxf(lmax, __shfl_xor_sync(0xffffffffu, lmax, o));
        float lsum = 0.f; cnt = 0;
        for (int kk = lane; kk < 197; kk += 32) {
            float e = expf(ls[cnt++] - lmax);
            pb[w * 197 + kk] = e; lsum += e;
        }
        #pragma unroll
        for (int o = 16; o; o >>= 1) lsum += __shfl_xor_sync(0xffffffffu, lsum, o);
        float inv = 1.f / lsum;
        __syncwarp();
        float a0 = 0.f, a1 = 0.f;
        for (int kk = 0; kk < 197; kk++) {
            float p = pb[w * 197 + kk];
            a0 += p * Vs[kk * 65 + lane];
            a1 += p * Vs[kk * 65 + lane + 32];
        }
        size_t oo = (size_t)(b * SQ + sq) * 768 + h * 64;
        outp[oo + lane]      = a0 * inv;
        outp[oo + lane + 32] = a1 * inv;
        __syncwarp();
    }
}

// ---------------- time attention: warp per (b,h,pos), 8 queries x 9 keys ----------------
__global__ void time_attn_k(const float* __restrict__ qkv, float* __restrict__ outp) {
    int g = blockIdx.x * 8 + (threadIdx.x >> 5);
    int lane = threadIdx.x & 31;
    if (g >= 48 * 196) return;
    int bh = g / 196, pos = g % 196;
    int b = bh / 12, h = bh % 12;
    float K0[9], K1[9], V0[9], V1[9];
    #pragma unroll
    for (int kk = 0; kk < 9; kk++) {
        int s = kk ? (1 + (kk - 1) * 196 + pos) : 0;
        size_t o = (size_t)(b * SQ + s) * 2304 + h * 64;
        K0[kk] = qkv[o + 768 + lane];  K1[kk] = qkv[o + 768 + lane + 32];
        V0[kk] = qkv[o + 1536 + lane]; V1[kk] = qkv[o + 1536 + lane + 32];
    }
    for (int fq = 0; fq < 8; fq++) {
        int sq = 1 + fq * 196 + pos;
        size_t oq = (size_t)(b * SQ + sq) * 2304 + h * 64;
        float q0 = qkv[oq + lane] * SCALEQ, q1 = qkv[oq + lane + 32] * SCALEQ;
        float sc[9];
        #pragma unroll
        for (int kk = 0; kk < 9; kk++) {
            float p = q0 * K0[kk] + q1 * K1[kk];
            #pragma unroll
            for (int o = 16; o; o >>= 1) p += __shfl_xor_sync(0xffffffffu, p, o);
            sc[kk] = p;
        }
        float mx = sc[0];
        #pragma unroll
        for (int kk = 1; kk < 9; kk++) mx = fmaxf(mx, sc[kk]);
        float den = 0.f;
        #pragma unroll
        for (int kk = 0; kk < 9; kk++) { sc[kk] = expf(sc[kk] - mx); den += sc[kk]; }
        float inv = 1.f / den;
        float a0 = 0.f, a1 = 0.f;
        #pragma unroll
        for (int kk = 0; kk < 9; kk++) { a0 += sc[kk] * V0[kk]; a1 += sc[kk] * V1[kk]; }
        size_t oo = (size_t)(b * SQ + sq) * 768 + h * 64;
        outp[oo + lane]      = a0 * inv;
        outp[oo + lane + 32] = a1 * inv;
    }
}

// ---------------- host orchestration ----------------
static void gemm(const float* A, const float* W, const float* bias, const float* res,
                 float* C, int M, int N, int K, int act) {
    dim3 g(N / 128, (M + 127) / 128);
    if (act) gemm_k<1><<<g, 256>>>(A, W, bias, res, C, M, N, K);
    else     gemm_k<0><<<g, 256>>>(A, W, bias, res, C, M, N, K);
}

extern "C" void kernel_launch(void* const* d_in, const int* in_sizes, int n_in,
                              void* d_out, int out_size) {
    const float* x       = (const float*)d_in[0];
    const float* patch_w = (const float*)d_in[1];
    const float* patch_b = (const float*)d_in[2];
    const float* cls_tok = (const float*)d_in[3];
    const float* pos     = (const float*)d_in[4];
    const float* temp    = (const float*)d_in[5];
    const float* n1s = (const float*)d_in[6],  *n1b = (const float*)d_in[7];
    const float* n2s = (const float*)d_in[8],  *n2b = (const float*)d_in[9];
    const float* n3s = (const float*)d_in[10], *n3b = (const float*)d_in[11];
    const float* aqw = (const float*)d_in[12], *aqb = (const float*)d_in[13];
    const float* apw = (const float*)d_in[14], *apb = (const float*)d_in[15];
    const float* tqw = (const float*)d_in[16], *tqb = (const float*)d_in[17];
    const float* tpw = (const float*)d_in[18], *tpb = (const float*)d_in[19];
    const float* f1w = (const float*)d_in[20], *f1b = (const float*)d_in[21];
    const float* f2w = (const float*)d_in[22], *f2b = (const float*)d_in[23];
    const float* nfs = (const float*)d_in[24], *nfb = (const float*)d_in[25];
    float* out = (float*)d_out;

    float *xt, *ln, *qkv, *attn, *res, *hid;
    cudaGetSymbolAddress((void**)&xt,   g_xt);
    cudaGetSymbolAddress((void**)&ln,   g_ln);
    cudaGetSymbolAddress((void**)&qkv,  g_qkv);
    cudaGetSymbolAddress((void**)&attn, g_attn);
    cudaGetSymbolAddress((void**)&res,  g_res);
    cudaGetSymbolAddress((void**)&hid,  g_hid);

    cudaFuncSetAttribute(space_attn_k, cudaFuncAttributeMaxDynamicSharedMemorySize, SPACE_SMEM);

    // ---- patch embedding ----
    im2col_k<<<(6272 * 768 + 255) / 256, 256>>>(x, hid);
    gemm(hid, patch_w, nullptr, nullptr, ln, 6272, 768, 768, 0);
    assemble_k<<<(TQ * DQ + 255) / 256, 256>>>(ln, patch_b, cls_tok, pos, temp, xt);

    for (int l = 0; l < LQ; l++) {
        // ---- time attention ----
        ln_k<<<TQ, 256>>>(xt, n3s + (size_t)l * DQ, n3b + (size_t)l * DQ, ln);
        gemm(ln, tqw + (size_t)l * 3 * DQ * DQ, tqb + (size_t)l * 3 * DQ, nullptr,
             qkv, TQ, 3 * DQ, DQ, 0);
        cls_attn_k<<<48, 256>>>(qkv, attn);
        time_attn_k<<<1176, 256>>>(qkv, attn);
        gemm(attn, tpw + (size_t)l * DQ * DQ, tpb + (size_t)l * DQ, xt,
             res, TQ, DQ, DQ, 0);                          // time_res = xt + t_out
        // ---- space attention ----
        ln_k<<<TQ, 256>>>(res, n1s + (size_t)l * DQ, n1b + (size_t)l * DQ, ln);
        gemm(ln, aqw + (size_t)l * 3 * DQ * DQ, aqb + (size_t)l * 3 * DQ, nullptr,
             qkv, TQ, 3 * DQ, DQ, 0);
        cls_attn_k<<<48, 256>>>(qkv, attn);
        space_attn_k<<<384, 256, SPACE_SMEM>>>(qkv, attn);
        gemm(attn, apw + (size_t)l * DQ * DQ, apb + (size_t)l * DQ, xt,
             res, TQ, DQ, DQ, 0);                          // space_res = xt + s_out
        // ---- MLP ----
        ln_k<<<TQ, 256>>>(res, n2s + (size_t)l * DQ, n2b + (size_t)l * DQ, ln);
        gemm(ln, f1w + (size_t)l * HIDQ * DQ, f1b + (size_t)l * HIDQ, nullptr,
             hid, TQ, HIDQ, DQ, 1);                        // GELU
        gemm(hid, f2w + (size_t)l * DQ * HIDQ, f2b + (size_t)l * DQ, res,
             xt, TQ, DQ, HIDQ, 0);                         // xt = space_res + mlp
    }

    final_ln_k<<<BQ, 256>>>(xt, nfs, nfb, out);
}

// round 2
// speedup vs baseline: 1.9595x; 1.9595x over previous
#include <cuda_runtime.h>
#include <cuda_bf16.h>
#include <stdint.h>
#include <math.h>

// ---------------- problem constants ----------------
#define BQ 4
#define FQ 8
#define HQ 12
#define DQ 768
#define SQ 1569                  // 1 + 8*196
#define TQ (BQ*SQ)               // 6276 tokens
#define HIDQ 3072
#define LQ 12
#define EPSQ 1e-6f
#define SCALEQ 0.125f            // 64^-0.5

// ---------------- scratch (static device globals; no allocations) ----------------
__device__ float g_xt  [(size_t)TQ*DQ];
__device__ float g_ln  [(size_t)TQ*DQ];
__device__ float g_qkv [(size_t)TQ*3*DQ];
__device__ float g_attn[(size_t)TQ*DQ];
__device__ float g_res [(size_t)TQ*DQ];
__device__ float g_hid [(size_t)TQ*HIDQ];   // also reused as im2col buffer

// ---------------- block reduce helper (256-thread blocks) ----------------
__device__ __forceinline__ float block_red(float v, int isMax) {
    __shared__ float red[8];
    int lane = threadIdx.x & 31, w = threadIdx.x >> 5;
    #pragma unroll
    for (int o = 16; o; o >>= 1) {
        float t = __shfl_xor_sync(0xffffffffu, v, o);
        v = isMax ? fmaxf(v, t) : (v + t);
    }
    __syncthreads();
    if (lane == 0) red[w] = v;
    __syncthreads();
    float t = red[0];
    #pragma unroll
    for (int i = 1; i < 8; i++) t = isMax ? fmaxf(t, red[i]) : (t + red[i]);
    return t;
}

// ---------------- im2col for patch embedding ----------------
__global__ void im2col_k(const float* __restrict__ x, float* __restrict__ out) {
    int idx = blockIdx.x * 256 + threadIdx.x;
    if (idx >= 6272 * 768) return;
    int r = idx / 768, c = idx % 768;
    int bf = r / 196, p = r % 196;
    int ph = p / 14, pw = p % 14;
    int ch = c >> 8, rem = c & 255;
    int i = rem >> 4, j = rem & 15;
    size_t off = (((size_t)bf * 3 + ch) * 224 + ph * 16 + i) * 224 + pw * 16 + j;
    out[idx] = x[off];
}

// ---------------- assemble tokens ----------------
__global__ void assemble_k(const float* __restrict__ pe,
                           const float* __restrict__ patch_b,
                           const float* __restrict__ cls_tok,
                           const float* __restrict__ pos,
                           const float* __restrict__ temp,
                           float* __restrict__ xt) {
    int idx = blockIdx.x * 256 + threadIdx.x;
    if (idx >= TQ * DQ) return;
    int t = idx / DQ, dd = idx % DQ;
    int b = t / SQ, s = t % SQ;
    float v;
    if (s == 0) {
        v = cls_tok[dd] + pos[dd];
    } else {
        int sp = s - 1, fr = sp / 196, p = sp % 196;
        v = pe[((size_t)(b * 8 + fr) * 196 + p) * 768 + dd] + patch_b[dd]
            + pos[(size_t)(1 + p) * 768 + dd] + temp[(size_t)fr * 768 + dd];
    }
    xt[idx] = v;
}

// ---------------- layernorm (row = 768) ----------------
__global__ void ln_k(const float* __restrict__ x, const float* __restrict__ sc,
                     const float* __restrict__ bi, float* __restrict__ y) {
    int row = blockIdx.x, tid = threadIdx.x;
    const float* xr = x + (size_t)row * DQ;
    float r0 = xr[tid], r1 = xr[tid + 256], r2 = xr[tid + 512];
    float mean = block_red(r0 + r1 + r2, 0) * (1.f / 768.f);
    float d0 = r0 - mean, d1 = r1 - mean, d2 = r2 - mean;
    float var = block_red(d0 * d0 + d1 * d1 + d2 * d2, 0) * (1.f / 768.f);
    float inv = rsqrtf(var + EPSQ);
    float* yr = y + (size_t)row * DQ;
    yr[tid]       = d0 * inv * sc[tid]       + bi[tid];
    yr[tid + 256] = d1 * inv * sc[tid + 256] + bi[tid + 256];
    yr[tid + 512] = d2 * inv * sc[tid + 512] + bi[tid + 512];
}

__global__ void final_ln_k(const float* __restrict__ xt, const float* __restrict__ sc,
                           const float* __restrict__ bi, float* __restrict__ out) {
    int b = blockIdx.x, tid = threadIdx.x;
    const float* xr = xt + (size_t)(b * SQ) * DQ;
    float r0 = xr[tid], r1 = xr[tid + 256], r2 = xr[tid + 512];
    float mean = block_red(r0 + r1 + r2, 0) * (1.f / 768.f);
    float d0 = r0 - mean, d1 = r1 - mean, d2 = r2 - mean;
    float var = block_red(d0 * d0 + d1 * d1 + d2 * d2, 0) * (1.f / 768.f);
    float inv = rsqrtf(var + EPSQ);
    float* yr = out + (size_t)b * DQ;
    yr[tid]       = d0 * inv * sc[tid]       + bi[tid];
    yr[tid + 256] = d1 * inv * sc[tid + 256] + bi[tid + 256];
    yr[tid + 512] = d2 * inv * sc[tid + 512] + bi[tid + 512];
}

// ============== bf16-split tensor-core GEMM ==============
// C[M,N] = A[M,K] @ W[N,K]^T (+bias) (+res) (+gelu), fp32-accurate via
// A ~ Ah+Al, W ~ Wh+Wl (bf16 each); C = Ah*Wh + Ah*Wl + Al*Wh.
// Block 128x128x32, 256 thr (8 warps, 2x4), warp tile 64x32, mma m16n8k16.

#define GLD 36                               // smem row stride (bf16 elems)
#define GEMM_SMEM (2 * 4 * 128 * GLD * 2)    // 2 stages * 4 arrays * 128*36 bf16

__device__ __forceinline__ uint32_t f2bf2(float x0, float x1) {
    __nv_bfloat162 h = __floats2bfloat162_rn(x0, x1);
    return *reinterpret_cast<uint32_t*>(&h);
}

__device__ __forceinline__ void mma16816(float* c,
        uint32_t a0, uint32_t a1, uint32_t a2, uint32_t a3,
        uint32_t b0, uint32_t b1) {
    asm volatile(
        "mma.sync.aligned.m16n8k16.row.col.f32.bf16.bf16.f32 "
        "{%0,%1,%2,%3}, {%4,%5,%6,%7}, {%8,%9}, {%0,%1,%2,%3};\n"
        : "+f"(c[0]), "+f"(c[1]), "+f"(c[2]), "+f"(c[3])
        : "r"(a0), "r"(a1), "r"(a2), "r"(a3), "r"(b0), "r"(b1));
}

// convert 4 fp32 -> hi/lo bf16 pairs and store to smem (two 4B stores each)
__device__ __forceinline__ void cvt_store(__nv_bfloat16* hi, __nv_bfloat16* lo,
                                          int row, int col, float4 v) {
    float h0 = __bfloat162float(__float2bfloat16_rn(v.x));
    float h1 = __bfloat162float(__float2bfloat16_rn(v.y));
    float h2 = __bfloat162float(__float2bfloat16_rn(v.z));
    float h3 = __bfloat162float(__float2bfloat16_rn(v.w));
    uint32_t* ph = (uint32_t*)&hi[row * GLD + col];
    uint32_t* pl = (uint32_t*)&lo[row * GLD + col];
    ph[0] = f2bf2(h0, h1); ph[1] = f2bf2(h2, h3);
    pl[0] = f2bf2(v.x - h0, v.y - h1); pl[1] = f2bf2(v.z - h2, v.w - h3);
}

template<int ACT>
__global__ void __launch_bounds__(256, 1) gemm_k(
    const float* __restrict__ A, const float* __restrict__ W,
    const float* __restrict__ bias, const float* __restrict__ res,
    float* __restrict__ C, int M, int N, int K) {
    extern __shared__ __nv_bfloat16 smem[];
    const int SARR = 128 * GLD;          // one array
    const int SSTG = 4 * SARR;           // one stage (Ah,Al,Bh,Bl)

    int tid = threadIdx.x;
    int lane = tid & 31, w = tid >> 5;
    int warpM = w >> 2, warpN = w & 3;   // 2 x 4
    int g = lane >> 2, q = lane & 3;
    int bm = blockIdx.y * 128, bn = blockIdx.x * 128;

    int lrow = tid >> 3;                 // 0..31
    int lcol = (tid & 7) * 4;            // 0..28

    float acc[4][4][4];
    #pragma unroll
    for (int i = 0; i < 4; i++)
        #pragma unroll
        for (int j = 0; j < 4; j++)
            #pragma unroll
            for (int c = 0; c < 4; c++) acc[i][j][c] = 0.f;

    const int iters = K >> 5;            // K/32
    float4 aReg[4], bReg[4];

    // prologue: load tile 0
    #pragma unroll
    for (int u = 0; u < 4; u++) {
        int row = u * 32 + lrow;
        int gm = bm + row;
        aReg[u] = (gm < M) ? *(const float4*)(A + (size_t)gm * K + lcol)
                           : make_float4(0.f, 0.f, 0.f, 0.f);
        bReg[u] = *(const float4*)(W + (size_t)(bn + row) * K + lcol);
    }
    {
        __nv_bfloat16* Ah = smem;            __nv_bfloat16* Al = smem + SARR;
        __nv_bfloat16* Bh = smem + 2 * SARR; __nv_bfloat16* Bl = smem + 3 * SARR;
        #pragma unroll
        for (int u = 0; u < 4; u++) {
            int row = u * 32 + lrow;
            cvt_store(Ah, Al, row, lcol, aReg[u]);
            cvt_store(Bh, Bl, row, lcol, bReg[u]);
        }
    }
    __syncthreads();

    for (int iter = 0; iter < iters; iter++) {
        int cur = iter & 1, nxt = cur ^ 1;
        bool hasNext = (iter + 1) < iters;
        if (hasNext) {
            int k0 = (iter + 1) << 5;
            #pragma unroll
            for (int u = 0; u < 4; u++) {
                int row = u * 32 + lrow;
                int gm = bm + row;
                aReg[u] = (gm < M) ? *(const float4*)(A + (size_t)gm * K + k0 + lcol)
                                   : make_float4(0.f, 0.f, 0.f, 0.f);
                bReg[u] = *(const float4*)(W + (size_t)(bn + row) * K + k0 + lcol);
            }
        }
        const __nv_bfloat16* Ah = smem + cur * SSTG;
        const __nv_bfloat16* Al = Ah + SARR;
        const __nv_bfloat16* Bh = Ah + 2 * SARR;
        const __nv_bfloat16* Bl = Ah + 3 * SARR;

        #pragma unroll
        for (int kk = 0; kk < 2; kk++) {
            int c0 = kk * 16 + q * 2;
            uint32_t ah[4][4], al[4][4], bh[4][2], bl[4][2];
            #pragma unroll
            for (int i = 0; i < 4; i++) {
                int r0 = warpM * 64 + i * 16 + g;
                const __nv_bfloat16* p0 = Ah + r0 * GLD + c0;
                const __nv_bfloat16* p1 = Ah + (r0 + 8) * GLD + c0;
                ah[i][0] = *(const uint32_t*)(p0);
                ah[i][1] = *(const uint32_t*)(p1);
                ah[i][2] = *(const uint32_t*)(p0 + 8);
                ah[i][3] = *(const uint32_t*)(p1 + 8);
                const __nv_bfloat16* q0 = Al + r0 * GLD + c0;
                const __nv_bfloat16* q1 = Al + (r0 + 8) * GLD + c0;
                al[i][0] = *(const uint32_t*)(q0);
                al[i][1] = *(const uint32_t*)(q1);
                al[i][2] = *(const uint32_t*)(q0 + 8);
                al[i][3] = *(const uint32_t*)(q1 + 8);
            }
            #pragma unroll
            for (int j = 0; j < 4; j++) {
                int nr = warpN * 32 + j * 8 + g;
                const __nv_bfloat16* p = Bh + nr * GLD + c0;
                bh[j][0] = *(const uint32_t*)(p);
                bh[j][1] = *(const uint32_t*)(p + 8);
                const __nv_bfloat16* pl = Bl + nr * GLD + c0;
                bl[j][0] = *(const uint32_t*)(pl);
                bl[j][1] = *(const uint32_t*)(pl + 8);
            }
            #pragma unroll
            for (int i = 0; i < 4; i++)
                #pragma unroll
                for (int j = 0; j < 4; j++) {
                    mma16816(acc[i][j], ah[i][0], ah[i][1], ah[i][2], ah[i][3],
                             bh[j][0], bh[j][1]);
                    mma16816(acc[i][j], ah[i][0], ah[i][1], ah[i][2], ah[i][3],
                             bl[j][0], bl[j][1]);
                    mma16816(acc[i][j], al[i][0], al[i][1], al[i][2], al[i][3],
                             bh[j][0], bh[j][1]);
                }
        }

        if (hasNext) {
            __nv_bfloat16* Ah2 = smem + nxt * SSTG;
            __nv_bfloat16* Al2 = Ah2 + SARR;
            __nv_bfloat16* Bh2 = Ah2 + 2 * SARR;
            __nv_bfloat16* Bl2 = Ah2 + 3 * SARR;
            #pragma unroll
            for (int u = 0; u < 4; u++) {
                int row = u * 32 + lrow;
                cvt_store(Ah2, Al2, row, lcol, aReg[u]);
                cvt_store(Bh2, Bl2, row, lcol, bReg[u]);
            }
        }
        __syncthreads();
    }

    // epilogue
    #pragma unroll
    for (int i = 0; i < 4; i++) {
        int m0 = bm + warpM * 64 + i * 16 + g;
        #pragma unroll
        for (int j = 0; j < 4; j++) {
            int n0 = bn + warpN * 32 + j * 8 + q * 2;
            float bx = bias ? bias[n0] : 0.f;
            float by = bias ? bias[n0 + 1] : 0.f;
            #pragma unroll
            for (int half = 0; half < 2; half++) {
                int m = m0 + half * 8;
                if (m >= M) continue;
                float v0 = acc[i][j][half * 2 + 0] + bx;
                float v1 = acc[i][j][half * 2 + 1] + by;
                if (res) {
                    const float* rp = res + (size_t)m * N + n0;
                    v0 += rp[0]; v1 += rp[1];
                }
                if (ACT == 1) {
                    v0 = 0.5f * v0 * (1.f + erff(v0 * 0.70710678118654752f));
                    v1 = 0.5f * v1 * (1.f + erff(v1 * 0.70710678118654752f));
                }
                float2* cp = (float2*)(C + (size_t)m * N + n0);
                *cp = make_float2(v0, v1);
            }
        }
    }
}

// ---------------- cls-row attention ----------------
__global__ void cls_attn_k(const float* __restrict__ qkv, float* __restrict__ outp) {
    __shared__ float sc[SQ];
    __shared__ float qv[64];
    __shared__ float op[256];
    int bh = blockIdx.x, b = bh / 12, h = bh % 12;
    int tid = threadIdx.x;
    size_t base = (size_t)(b * SQ) * 2304 + (size_t)h * 64;
    if (tid < 64) qv[tid] = qkv[base + tid] * SCALEQ;
    __syncthreads();
    float lmax = -1e30f;
    for (int s = tid; s < SQ; s += 256) {
        const float* kp = qkv + (size_t)(b * SQ + s) * 2304 + 768 + h * 64;
        float d = 0.f;
        #pragma unroll
        for (int i = 0; i < 64; i++) d += qv[i] * kp[i];
        sc[s] = d; lmax = fmaxf(lmax, d);
    }
    float mx = block_red(lmax, 1);
    float lsum = 0.f;
    for (int s = tid; s < SQ; s += 256) {
        float e = expf(sc[s] - mx);
        sc[s] = e; lsum += e;
    }
    float den = block_red(lsum, 0);
    __syncthreads();
    int part = tid >> 6, d = tid & 63;
    float acc = 0.f;
    for (int s = part; s < SQ; s += 4)
        acc += sc[s] * qkv[(size_t)(b * SQ + s) * 2304 + 1536 + h * 64 + d];
    op[tid] = acc;
    __syncthreads();
    if (tid < 64) {
        float t = op[tid] + op[tid + 64] + op[tid + 128] + op[tid + 192];
        outp[(size_t)(b * SQ) * 768 + h * 64 + tid] = t / den;
    }
}

// ---------------- space attention ----------------
#define SPACE_SMEM ((197*65*2 + 8*197 + 8*64) * 4)
__global__ void space_attn_k(const float* __restrict__ qkv, float* __restrict__ outp) {
    extern __shared__ float sm[];
    float* Ks = sm;
    float* Vs = Ks + 197 * 65;
    float* pb = Vs + 197 * 65;
    float* qb = pb + 8 * 197;
    int blk = blockIdx.x;
    int fr = blk % 8, h = (blk / 8) % 12, b = blk / 96;
    int tid = threadIdx.x, lane = tid & 31, w = tid >> 5;
    for (int idx = tid; idx < 197 * 64; idx += 256) {
        int kk = idx >> 6, d = idx & 63;
        int s = kk ? (1 + fr * 196 + kk - 1) : 0;
        size_t o = (size_t)(b * SQ + s) * 2304 + h * 64;
        Ks[kk * 65 + d] = qkv[o + 768 + d];
        Vs[kk * 65 + d] = qkv[o + 1536 + d];
    }
    __syncthreads();
    for (int qi = w; qi < 196; qi += 8) {
        int sq = 1 + fr * 196 + qi;
        size_t oq = (size_t)(b * SQ + sq) * 2304 + h * 64;
        qb[w * 64 + lane]      = qkv[oq + lane] * SCALEQ;
        qb[w * 64 + lane + 32] = qkv[oq + lane + 32] * SCALEQ;
        __syncwarp();
        float ls[7];
        float lmax = -1e30f;
        int cnt = 0;
        for (int kk = lane; kk < 197; kk += 32) {
            float s = 0.f;
            #pragma unroll
            for (int d = 0; d < 64; d++) s += qb[w * 64 + d] * Ks[kk * 65 + d];
            ls[cnt++] = s; lmax = fmaxf(lmax, s);
        }
        #pragma unroll
        for (int o = 16; o; o >>= 1) lmax = fmaxf(lmax, __shfl_xor_sync(0xffffffffu, lmax, o));
        float lsum = 0.f; cnt = 0;
        for (int kk = lane; kk < 197; kk += 32) {
            float e = expf(ls[cnt++] - lmax);
            pb[w * 197 + kk] = e; lsum += e;
        }
        #pragma unroll
        for (int o = 16; o; o >>= 1) lsum += __shfl_xor_sync(0xffffffffu, lsum, o);
        float inv = 1.f / lsum;
        __syncwarp();
        float a0 = 0.f, a1 = 0.f;
        for (int kk = 0; kk < 197; kk++) {
            float p = pb[w * 197 + kk];
            a0 += p * Vs[kk * 65 + lane];
            a1 += p * Vs[kk * 65 + lane + 32];
        }
        size_t oo = (size_t)(b * SQ + sq) * 768 + h * 64;
        outp[oo + lane]      = a0 * inv;
        outp[oo + lane + 32] = a1 * inv;
        __syncwarp();
    }
}

// ---------------- time attention ----------------
__global__ void time_attn_k(const float* __restrict__ qkv, float* __restrict__ outp) {
    int g = blockIdx.x * 8 + (threadIdx.x >> 5);
    int lane = threadIdx.x & 31;
    if (g >= 48 * 196) return;
    int bh = g / 196, pos = g % 196;
    int b = bh / 12, h = bh % 12;
    float K0[9], K1[9], V0[9], V1[9];
    #pragma unroll
    for (int kk = 0; kk < 9; kk++) {
        int s = kk ? (1 + (kk - 1) * 196 + pos) : 0;
        size_t o = (size_t)(b * SQ + s) * 2304 + h * 64;
        K0[kk] = qkv[o + 768 + lane];  K1[kk] = qkv[o + 768 + lane + 32];
        V0[kk] = qkv[o + 1536 + lane]; V1[kk] = qkv[o + 1536 + lane + 32];
    }
    for (int fq = 0; fq < 8; fq++) {
        int sq = 1 + fq * 196 + pos;
        size_t oq = (size_t)(b * SQ + sq) * 2304 + h * 64;
        float q0 = qkv[oq + lane] * SCALEQ, q1 = qkv[oq + lane + 32] * SCALEQ;
        float sc[9];
        #pragma unroll
        for (int kk = 0; kk < 9; kk++) {
            float p = q0 * K0[kk] + q1 * K1[kk];
            #pragma unroll
            for (int o = 16; o; o >>= 1) p += __shfl_xor_sync(0xffffffffu, p, o);
            sc[kk] = p;
        }
        float mx = sc[0];
        #pragma unroll
        for (int kk = 1; kk < 9; kk++) mx = fmaxf(mx, sc[kk]);
        float den = 0.f;
        #pragma unroll
        for (int kk = 0; kk < 9; kk++) { sc[kk] = expf(sc[kk] - mx); den += sc[kk]; }
        float inv = 1.f / den;
        float a0 = 0.f, a1 = 0.f;
        #pragma unroll
        for (int kk = 0; kk < 9; kk++) { a0 += sc[kk] * V0[kk]; a1 += sc[kk] * V1[kk]; }
        size_t oo = (size_t)(b * SQ + sq) * 768 + h * 64;
        outp[oo + lane]      = a0 * inv;
        outp[oo + lane + 32] = a1 * inv;
    }
}

// ---------------- host orchestration ----------------
static void gemm(const float* A, const float* W, const float* bias, const float* res,
                 float* C, int M, int N, int K, int act) {
    dim3 g(N / 128, (M + 127) / 128);
    if (act) gemm_k<1><<<g, 256, GEMM_SMEM>>>(A, W, bias, res, C, M, N, K);
    else     gemm_k<0><<<g, 256, GEMM_SMEM>>>(A, W, bias, res, C, M, N, K);
}

extern "C" void kernel_launch(void* const* d_in, const int* in_sizes, int n_in,
                              void* d_out, int out_size) {
    const float* x       = (const float*)d_in[0];
    const float* patch_w = (const float*)d_in[1];
    const float* patch_b = (const float*)d_in[2];
    const float* cls_tok = (const float*)d_in[3];
    const float* pos     = (const float*)d_in[4];
    const float* temp    = (const float*)d_in[5];
    const float* n1s = (const float*)d_in[6],  *n1b = (const float*)d_in[7];
    const float* n2s = (const float*)d_in[8],  *n2b = (const float*)d_in[9];
    const float* n3s = (const float*)d_in[10], *n3b = (const float*)d_in[11];
    const float* aqw = (const float*)d_in[12], *aqb = (const float*)d_in[13];
    const float* apw = (const float*)d_in[14], *apb = (const float*)d_in[15];
    const float* tqw = (const float*)d_in[16], *tqb = (const float*)d_in[17];
    const float* tpw = (const float*)d_in[18], *tpb = (const float*)d_in[19];
    const float* f1w = (const float*)d_in[20], *f1b = (const float*)d_in[21];
    const float* f2w = (const float*)d_in[22], *f2b = (const float*)d_in[23];
    const float* nfs = (const float*)d_in[24], *nfb = (const float*)d_in[25];
    float* out = (float*)d_out;

    float *xt, *ln, *qkv, *attn, *res, *hid;
    cudaGetSymbolAddress((void**)&xt,   g_xt);
    cudaGetSymbolAddress((void**)&ln,   g_ln);
    cudaGetSymbolAddress((void**)&qkv,  g_qkv);
    cudaGetSymbolAddress((void**)&attn, g_attn);
    cudaGetSymbolAddress((void**)&res,  g_res);
    cudaGetSymbolAddress((void**)&hid,  g_hid);

    cudaFuncSetAttribute(space_attn_k, cudaFuncAttributeMaxDynamicSharedMemorySize, SPACE_SMEM);
    cudaFuncSetAttribute(gemm_k<0>, cudaFuncAttributeMaxDynamicSharedMemorySize, GEMM_SMEM);
    cudaFuncSetAttribute(gemm_k<1>, cudaFuncAttributeMaxDynamicSharedMemorySize, GEMM_SMEM);

    // ---- patch embedding ----
    im2col_k<<<(6272 * 768 + 255) / 256, 256>>>(x, hid);
    gemm(hid, patch_w, nullptr, nullptr, ln, 6272, 768, 768, 0);
    assemble_k<<<(TQ * DQ + 255) / 256, 256>>>(ln, patch_b, cls_tok, pos, temp, xt);

    for (int l = 0; l < LQ; l++) {
        // ---- time attention ----
        ln_k<<<TQ, 256>>>(xt, n3s + (size_t)l * DQ, n3b + (size_t)l * DQ, ln);
        gemm(ln, tqw + (size_t)l * 3 * DQ * DQ, tqb + (size_t)l * 3 * DQ, nullptr,
             qkv, TQ, 3 * DQ, DQ, 0);
        cls_attn_k<<<48, 256>>>(qkv, attn);
        time_attn_k<<<1176, 256>>>(qkv, attn);
        gemm(attn, tpw + (size_t)l * DQ * DQ, tpb + (size_t)l * DQ, xt,
             res, TQ, DQ, DQ, 0);
        // ---- space attention ----
        ln_k<<<TQ, 256>>>(res, n1s + (size_t)l * DQ, n1b + (size_t)l * DQ, ln);
        gemm(ln, aqw + (size_t)l * 3 * DQ * DQ, aqb + (size_t)l * 3 * DQ, nullptr,
             qkv, TQ, 3 * DQ, DQ, 0);
        cls_attn_k<<<48, 256>>>(qkv, attn);
        space_attn_k<<<384, 256, SPACE_SMEM>>>(qkv, attn);
        gemm(attn, apw + (size_t)l * DQ * DQ, apb + (size_t)l * DQ, xt,
             res, TQ, DQ, DQ, 0);
        // ---- MLP ----
        ln_k<<<TQ, 256>>>(res, n2s + (size_t)l * DQ, n2b + (size_t)l * DQ, ln);
        gemm(ln, f1w + (size_t)l * HIDQ * DQ, f1b + (size_t)l * HIDQ, nullptr,
             hid, TQ, HIDQ, DQ, 1);
        gemm(hid, f2w + (size_t)l * DQ * HIDQ, f2b + (size_t)l * DQ, res,
             xt, TQ, DQ, HIDQ, 0);
    }

    final_ln_k<<<BQ, 256>>>(xt, nfs, nfb, out);
}